// round 9
// baseline (speedup 1.0000x reference)
#include <cuda_runtime.h>
#include <math.h>

#define KN 32
#define KC 64
#define KT 400
#define KV 27
#define KS 2

typedef unsigned long long u64;

// ---------------- device scratch ----------------
__device__ float g_part[20 * KN * KS * KV * KV];
__device__ float g_att [KN * KS * KV * KV];
__device__ float g_y4  [KN * KC * KT * KV];

__device__ __forceinline__ float lrelu(float x) { return x > 0.f ? x : 0.1f * x; }

__device__ __forceinline__ void ffma2(u64& d, u64 a, u64 b) {
  asm("fma.rn.f32x2 %0, %1, %2, %0;" : "+l"(d) : "l"(a), "l"(b));
}
__device__ __forceinline__ u64 bcast2(float w) {
  u64 r; asm("mov.b64 %0, {%1, %1};" : "=l"(r) : "f"(w)); return r;
}
__device__ __forceinline__ float2 unpk(u64 v) {
  float2 f; asm("mov.b64 {%0, %1}, %2;" : "=f"(f.x), "=f"(f.y) : "l"(v)); return f;
}

// ============================================================================
// Kernel A: attention Gram logits. Per block: (n, s, 20-t chunk), 5 groups of 4t.
// (R4 structure; QK GEMM converted to f32x2.)
// ============================================================================
__global__ void kA(const float* __restrict__ x, const float* __restrict__ pe,
                   const float* __restrict__ W_in, const float* __restrict__ b_in) {
  extern __shared__ float sm[];
  float* WQKT = sm;
  float* BQK  = sm + 2048;
  float* Ys   = sm + 2080;
  float* QKs  = sm + 8992;
  const int tid = threadIdx.x;
  const int chunk = blockIdx.x, s = blockIdx.y, n = blockIdx.z;

  for (int j = tid; j < 2048; j += 224) {
    int cc = j >> 5, r = j & 31;
    int row = (r < 16) ? (s * 16 + r) : (32 + s * 16 + (r - 16));
    WQKT[cc * 32 + r] = W_in[row * 64 + cc];
  }
  if (tid < 32) {
    int r = tid;
    int row = (r < 16) ? (s * 16 + r) : (32 + s * 16 + (r - 16));
    BQK[r] = b_in[row];
  }
  float g0 = 0.f, g1 = 0.f, g2 = 0.f, g3 = 0.f;
  __syncthreads();

  for (int grp = 0; grp < 5; ++grp) {
    const int t0 = chunk * 20 + grp * 4;
    for (int j = tid; j < 64 * 108; j += 224) {
      int cc = j / 108, r = j % 108;
      int tt = r / 27, u = r % 27;
      int t = t0 + tt;
      Ys[cc * 108 + u * 4 + tt] =
          x[((n * 64 + cc) * 400 + t) * 27 + u] + pe[(cc * 400 + t) * 27 + u];
    }
    __syncthreads();

    if (tid < 216) {
      const int rg = tid / 27, colg = tid % 27;
      u64 acc[8];
      #pragma unroll
      for (int i = 0; i < 8; ++i) acc[i] = 0ull;
      #pragma unroll 4
      for (int cc = 0; cc < 64; ++cc) {
        float4 w = *(const float4*)&WQKT[cc * 32 + rg * 4];
        ulonglong2 y = *(const ulonglong2*)&Ys[cc * 108 + colg * 4];
        u64 wb;
        wb = bcast2(w.x); ffma2(acc[0], wb, y.x); ffma2(acc[1], wb, y.y);
        wb = bcast2(w.y); ffma2(acc[2], wb, y.x); ffma2(acc[3], wb, y.y);
        wb = bcast2(w.z); ffma2(acc[4], wb, y.x); ffma2(acc[5], wb, y.y);
        wb = bcast2(w.w); ffma2(acc[6], wb, y.x); ffma2(acc[7], wb, y.y);
      }
      #pragma unroll
      for (int r = 0; r < 4; ++r) {
        float b = BQK[rg * 4 + r];
        float2 A0 = unpk(acc[r * 2]);
        float2 A1 = unpk(acc[r * 2 + 1]);
        *(float4*)&QKs[(rg * 4 + r) * 108 + colg * 4] =
            make_float4(A0.x + b, A0.y + b, A1.x + b, A1.y + b);
      }
    }
    __syncthreads();

    #pragma unroll
    for (int ii = 0; ii < 4; ++ii) {
      int p = tid + 224 * ii;
      if (p < 729) {
        int u = p / 27, vv = p % 27;
        float acc = 0.f;
        #pragma unroll 4
        for (int c = 0; c < 16; ++c) {
          float4 q = *(const float4*)&QKs[c * 108 + u * 4];
          float4 k = *(const float4*)&QKs[(16 + c) * 108 + vv * 4];
          acc += q.x * k.x + q.y * k.y + q.z * k.z + q.w * k.w;
        }
        if (ii == 0) g0 += acc; else if (ii == 1) g1 += acc;
        else if (ii == 2) g2 += acc; else g3 += acc;
      }
    }
    __syncthreads();
  }

  const int base = (chunk * 64 + n * 2 + s) * 729;
  g_part[base + tid] = g0;
  g_part[base + tid + 224] = g1;
  g_part[base + tid + 448] = g2;
  if (tid + 672 < 729) g_part[base + tid + 672] = g3;
}

// ============================================================================
// Kernel B: reduce 20 partials, tanh scale.
// ============================================================================
__global__ void kB(const float* __restrict__ alphas, const float* __restrict__ att0) {
  int idx = blockIdx.x * 256 + threadIdx.x;
  if (idx >= KN * KS * 729) return;
  int p = idx % 729;
  int s = (idx / 729) & 1;
  float sum = 0.f;
  #pragma unroll
  for (int ch = 0; ch < 20; ++ch) sum += g_part[ch * 46656 + idx];
  g_att[idx] = tanhf(sum * (1.0f / 6400.0f)) * alphas[s] + att0[s * 729 + p];
}

// ============================================================================
// Kernel C: per (n, 4-t tile), 448 threads, 2 CTAs/SM. cols = tt*28+v (112).
// y2 column-major thread map: lanes = adjacent col pairs -> conflict-free STS,
// broadcast x, contiguous u64 att loads, f32x2 accumulation.
// smem floats: WB[64][64]@0 (4096) | ATT@4096 (1512) | CAO@5608 CBO@5672
//   CAF@5736 CBF@5800 | XS[64][112]@5864 (7168) | YB[64][112]@13032 (7168)
// total 20200 f = 80800 B
// ============================================================================
__device__ __forceinline__ void kc_y2(float* sm, int S, int colp, int cq8) {
  const int ATT = 4096, XS = 5864, YB = 13032;
  const int col0 = colp * 2;
  const int tt = col0 / 28, v0 = col0 % 28;
  #pragma unroll 2
  for (int ci = 0; ci < 8; ++ci) {
    const int c = cq8 * 8 + ci;
    u64 acc = 0ull;
    const float* xr = &sm[XS + c * 112 + tt * 28];
    const float* ar = &sm[ATT + S * 756 + v0];
    #pragma unroll
    for (int u = 0; u < 27; ++u) {
      u64 ap = *(const u64*)&ar[u * 28];
      u64 xv = bcast2(xr[u]);
      ffma2(acc, xv, ap);
    }
    *(u64*)&sm[YB + c * 112 + col0] = acc;
  }
}

__device__ __forceinline__ void kc_gemm(const float* sm, int og, int cg, u64* acc) {
  const int YB = 13032;
  #pragma unroll 4
  for (int k = 0; k < 64; ++k) {
    const float* wr = &sm[k * 64 + og * 8];
    float4 wa = *(const float4*)wr;
    float4 wb = *(const float4*)(wr + 4);
    u64 y = *(const u64*)&sm[YB + k * 112 + cg * 2];
    ffma2(acc[0], bcast2(wa.x), y);
    ffma2(acc[1], bcast2(wa.y), y);
    ffma2(acc[2], bcast2(wa.z), y);
    ffma2(acc[3], bcast2(wa.w), y);
    ffma2(acc[4], bcast2(wb.x), y);
    ffma2(acc[5], bcast2(wb.y), y);
    ffma2(acc[6], bcast2(wb.z), y);
    ffma2(acc[7], bcast2(wb.w), y);
  }
}

__global__ void __launch_bounds__(448, 2)
kC(const float* __restrict__ x,
   const float* __restrict__ W_out, const float* __restrict__ b_out,
   const float* __restrict__ gm_out, const float* __restrict__ be_out,
   const float* __restrict__ m_out, const float* __restrict__ v_out,
   const float* __restrict__ W_ff, const float* __restrict__ b_ff,
   const float* __restrict__ gm_ff, const float* __restrict__ be_ff,
   const float* __restrict__ m_ff, const float* __restrict__ v_ff) {
  extern __shared__ float sm[];
  const int ATT = 4096, CAO = 5608, CBO = 5672, CAF = 5736, CBF = 5800;
  const int XS = 5864, YB = 13032;
  const int tid = threadIdx.x;
  const int n = blockIdx.y;
  const int t0 = blockIdx.x * 4;

  for (int j = tid; j < 7168; j += 448) {
    int c = j / 112, col = j % 112, tt = col / 28, v = col % 28;
    sm[XS + j] = (v < 27) ? x[((n * 64 + c) * 400 + t0 + tt) * 27 + v] : 0.f;
  }
  for (int j = tid; j < 1512; j += 448) {
    int s = j / 756, r = j % 756, u = r / 28, v = r % 28;
    sm[ATT + j] = (v < 27) ? g_att[(n * 2 + s) * 729 + u * 27 + v] : 0.f;
  }
  for (int j = tid; j < 4096; j += 448) {      // W_out s=0, [k][o]
    int k = j >> 6, o = j & 63;
    sm[j] = W_out[o * 128 + k];
  }
  if (tid < 64) {
    float a = gm_out[tid] * rsqrtf(v_out[tid] + 1e-5f);
    sm[CAO + tid] = a;
    sm[CBO + tid] = (b_out[tid] - m_out[tid]) * a + be_out[tid];
    float af = gm_ff[tid] * rsqrtf(v_ff[tid] + 1e-5f);
    sm[CAF + tid] = af;
    sm[CBF + tid] = (b_ff[tid] - m_ff[tid]) * af + be_ff[tid];
  }
  __syncthreads();

  const int colp = tid % 56, cq8 = tid / 56;   // y2 map: lanes over col pairs
  const int og = tid / 56, cg = tid % 56;      // GEMM map
  u64 acc[8];
  #pragma unroll
  for (int i = 0; i < 8; ++i) acc[i] = 0ull;

  // s = 0
  kc_y2(sm, 0, colp, cq8);
  __syncthreads();
  kc_gemm(sm, og, cg, acc);
  __syncthreads();

  // s = 1: swap weight half, recompute y2
  for (int j = tid; j < 4096; j += 448) {
    int k = j >> 6, o = j & 63;
    sm[j] = W_out[o * 128 + 64 + k];
  }
  kc_y2(sm, 1, colp, cq8);
  __syncthreads();
  kc_gemm(sm, og, cg, acc);
  __syncthreads();

  // epilogue 1: y3 -> YB ; load W_ff
  for (int j = tid; j < 4096; j += 448) {
    int k = j >> 6, o = j & 63;
    sm[j] = W_ff[o * 64 + k];
  }
  #pragma unroll
  for (int jo = 0; jo < 8; ++jo) {
    int o = og * 8 + jo;
    float a = sm[CAO + o], b = sm[CBO + o];
    float2 A = unpk(acc[jo]);
    float2 xv = *(const float2*)&sm[XS + o * 112 + cg * 2];
    float r0 = lrelu(xv.x + A.x * a + b);
    float r1 = lrelu(xv.y + A.y * a + b);
    *(float2*)&sm[YB + o * 112 + cg * 2] = make_float2(r0, r1);
  }
  #pragma unroll
  for (int i = 0; i < 8; ++i) acc[i] = 0ull;
  __syncthreads();

  kc_gemm(sm, og, cg, acc);

  // epilogue 2: y4 -> global
  #pragma unroll
  for (int jo = 0; jo < 8; ++jo) {
    int o = og * 8 + jo;
    float a = sm[CAF + o], b = sm[CBF + o];
    float2 A = unpk(acc[jo]);
    float rv[2] = {A.x, A.y};
    #pragma unroll
    for (int e = 0; e < 2; ++e) {
      int col = cg * 2 + e;
      int tt = col / 28, v = col % 28;
      if (v < 27) {
        float r = lrelu(sm[XS + o * 112 + col] + rv[e] * a + b);
        g_y4[((long)(n * 64 + o) * 400 + t0 + tt) * 27 + v] = r;
      }
    }
  }
}

// ============================================================================
// Kernel D: temporal conv (exact R4 version: 224 thr, 2 CTAs/SM, phased W).
// smem: WB[96][64]@0 (6144) | YS[64][280]@6144 (17920) | CAT@24064 CBT@24128
// total 24192 f = 96768 B
// ============================================================================
__global__ void __launch_bounds__(224, 2)
kD(const float* __restrict__ W_t, const float* __restrict__ b_t,
   const float* __restrict__ gm_t, const float* __restrict__ be_t,
   const float* __restrict__ m_t, const float* __restrict__ v_t,
   float* __restrict__ out) {
  extern __shared__ float sm[];
  const int YS = 6144, CAT = 24064, CBT = 24128;
  const int tid = threadIdx.x;
  const int n = blockIdx.y;
  const int t0 = blockIdx.x * 8;

  for (int j = tid; j < 17920; j += 224) {
    int i = j / 280, r = j % 280, tl = r / 28, v = r % 28;
    int t = t0 - 1 + tl;
    sm[YS + j] = (v < 27 && t >= 0 && t < 400)
                 ? g_y4[((long)(n * 64 + i) * 400 + t) * 27 + v] : 0.f;
  }
  if (tid < 64) {
    float a = gm_t[tid] * rsqrtf(v_t[tid] + 1e-5f);
    sm[CAT + tid] = a;
    sm[CBT + tid] = (b_t[tid] - m_t[tid]) * a + be_t[tid];
  }

  const int og = tid / 28, cg = tid % 28;
  u64 acc[32];
  #pragma unroll
  for (int i = 0; i < 32; ++i) acc[i] = 0ull;

  for (int p = 0; p < 2; ++p) {
    __syncthreads();
    for (int j = tid; j < 6144; j += 224) {
      int o = j / 96, r = j % 96;      // r = il*3+kk
      sm[r * 64 + o] = W_t[o * 192 + p * 96 + r];
    }
    __syncthreads();

    #pragma unroll 2
    for (int il = 0; il < 32; ++il) {
      const int i = p * 32 + il;
      #pragma unroll
      for (int kk = 0; kk < 3; ++kk) {
        const float* wr = &sm[(il * 3 + kk) * 64 + og * 8];
        float4 wa = *(const float4*)wr;
        float4 wb = *(const float4*)(wr + 4);
        ulonglong2 ya = *(const ulonglong2*)&sm[YS + i * 280 + kk * 28 + cg * 4];
        ulonglong2 yb = *(const ulonglong2*)&sm[YS + i * 280 + kk * 28 + 112 + cg * 4];
        u64 w;
        w = bcast2(wa.x); ffma2(acc[0],  w, ya.x); ffma2(acc[1],  w, ya.y); ffma2(acc[2],  w, yb.x); ffma2(acc[3],  w, yb.y);
        w = bcast2(wa.y); ffma2(acc[4],  w, ya.x); ffma2(acc[5],  w, ya.y); ffma2(acc[6],  w, yb.x); ffma2(acc[7],  w, yb.y);
        w = bcast2(wa.z); ffma2(acc[8],  w, ya.x); ffma2(acc[9],  w, ya.y); ffma2(acc[10], w, yb.x); ffma2(acc[11], w, yb.y);
        w = bcast2(wa.w); ffma2(acc[12], w, ya.x); ffma2(acc[13], w, ya.y); ffma2(acc[14], w, yb.x); ffma2(acc[15], w, yb.y);
        w = bcast2(wb.x); ffma2(acc[16], w, ya.x); ffma2(acc[17], w, ya.y); ffma2(acc[18], w, yb.x); ffma2(acc[19], w, yb.y);
        w = bcast2(wb.y); ffma2(acc[20], w, ya.x); ffma2(acc[21], w, ya.y); ffma2(acc[22], w, yb.x); ffma2(acc[23], w, yb.y);
        w = bcast2(wb.z); ffma2(acc[24], w, ya.x); ffma2(acc[25], w, ya.y); ffma2(acc[26], w, yb.x); ffma2(acc[27], w, yb.y);
        w = bcast2(wb.w); ffma2(acc[28], w, ya.x); ffma2(acc[29], w, ya.y); ffma2(acc[30], w, yb.x); ffma2(acc[31], w, yb.y);
      }
    }
  }

  #pragma unroll
  for (int jo = 0; jo < 8; ++jo) {
    int o = og * 8 + jo;
    float a = sm[CAT + o], b = sm[CBT + o];
    #pragma unroll
    for (int h = 0; h < 2; ++h) {
      float2 A0 = unpk(acc[jo * 4 + h * 2]);
      float2 A1 = unpk(acc[jo * 4 + h * 2 + 1]);
      float rv[4] = {A0.x, A0.y, A1.x, A1.y};
      int base = h * 112 + cg * 4;
      #pragma unroll
      for (int e = 0; e < 4; ++e) {
        int col = base + e;
        int tt = col / 28, v = col % 28;
        if (v < 27) {
          float y = sm[YS + o * 280 + (tt + 1) * 28 + v];   // residual y4
          float r = lrelu(y + rv[e] * a + b);
          out[((long)(n * 64 + o) * 400 + t0 + tt) * 27 + v] = r;
        }
      }
    }
  }
}

// ============================================================================
extern "C" void kernel_launch(void* const* d_in, const int* in_sizes, int n_in,
                              void* d_out, int out_size) {
  const float* x      = (const float*)d_in[0];
  const float* pe     = (const float*)d_in[1];
  const float* W_in   = (const float*)d_in[2];
  const float* b_in   = (const float*)d_in[3];
  const float* alphas = (const float*)d_in[4];
  const float* att0   = (const float*)d_in[5];
  const float* W_out  = (const float*)d_in[6];
  const float* b_out  = (const float*)d_in[7];
  const float* g_out  = (const float*)d_in[8];
  const float* be_out = (const float*)d_in[9];
  const float* m_out  = (const float*)d_in[10];
  const float* v_out  = (const float*)d_in[11];
  const float* W_ff   = (const float*)d_in[12];
  const float* b_ff   = (const float*)d_in[13];
  const float* g_ff   = (const float*)d_in[14];
  const float* be_ff  = (const float*)d_in[15];
  const float* m_ff   = (const float*)d_in[16];
  const float* v_ff   = (const float*)d_in[17];
  const float* W_t    = (const float*)d_in[18];
  const float* b_t    = (const float*)d_in[19];
  const float* g_t    = (const float*)d_in[20];
  const float* be_t   = (const float*)d_in[21];
  const float* m_t    = (const float*)d_in[22];
  const float* v_t    = (const float*)d_in[23];
  float* out = (float*)d_out;

  cudaFuncSetAttribute(kA, cudaFuncAttributeMaxDynamicSharedMemorySize, 49792);
  cudaFuncSetAttribute(kC, cudaFuncAttributeMaxDynamicSharedMemorySize, 80800);
  cudaFuncSetAttribute(kD, cudaFuncAttributeMaxDynamicSharedMemorySize, 96768);

  kA<<<dim3(20, 2, 32), 224, 49792>>>(x, pe, W_in, b_in);
  kB<<<(KN * KS * 729 + 255) / 256, 256>>>(alphas, att0);
  kC<<<dim3(100, 32), 448, 80800>>>(x, W_out, b_out, g_out, be_out, m_out, v_out,
                                    W_ff, b_ff, g_ff, be_ff, m_ff, v_ff);
  kD<<<dim3(50, 32), 224, 96768>>>(W_t, b_t, g_t, be_t, m_t, v_t, out);
}

// round 10
// speedup vs baseline: 1.8370x; 1.8370x over previous
#include <cuda_runtime.h>
#include <math.h>

#define KN 32
#define KC 64
#define KT 400
#define KV 27
#define KS 2

typedef unsigned long long u64;

// ---------------- device scratch ----------------
__device__ float g_part[20 * KN * KS * KV * KV];
__device__ float g_att [KN * KS * KV * KV];
__device__ float g_y4  [KN * KC * KT * KV];

__device__ __forceinline__ float lrelu(float x) { return x > 0.f ? x : 0.1f * x; }

__device__ __forceinline__ void ffma2(u64& d, u64 a, u64 b) {
  asm("fma.rn.f32x2 %0, %1, %2, %0;" : "+l"(d) : "l"(a), "l"(b));
}
__device__ __forceinline__ u64 bcast2(float w) {
  u64 r; asm("mov.b64 %0, {%1, %1};" : "=l"(r) : "f"(w)); return r;
}
__device__ __forceinline__ float2 unpk(u64 v) {
  float2 f; asm("mov.b64 {%0, %1}, %2;" : "=f"(f.x), "=f"(f.y) : "l"(v)); return f;
}

// ============================================================================
// Kernel A: attention Gram logits (unchanged from R9 — passed).
// ============================================================================
__global__ void kA(const float* __restrict__ x, const float* __restrict__ pe,
                   const float* __restrict__ W_in, const float* __restrict__ b_in) {
  extern __shared__ float sm[];
  float* WQKT = sm;
  float* BQK  = sm + 2048;
  float* Ys   = sm + 2080;
  float* QKs  = sm + 8992;
  const int tid = threadIdx.x;
  const int chunk = blockIdx.x, s = blockIdx.y, n = blockIdx.z;

  for (int j = tid; j < 2048; j += 224) {
    int cc = j >> 5, r = j & 31;
    int row = (r < 16) ? (s * 16 + r) : (32 + s * 16 + (r - 16));
    WQKT[cc * 32 + r] = W_in[row * 64 + cc];
  }
  if (tid < 32) {
    int r = tid;
    int row = (r < 16) ? (s * 16 + r) : (32 + s * 16 + (r - 16));
    BQK[r] = b_in[row];
  }
  float g0 = 0.f, g1 = 0.f, g2 = 0.f, g3 = 0.f;
  __syncthreads();

  for (int grp = 0; grp < 5; ++grp) {
    const int t0 = chunk * 20 + grp * 4;
    for (int j = tid; j < 64 * 108; j += 224) {
      int cc = j / 108, r = j % 108;
      int tt = r / 27, u = r % 27;
      int t = t0 + tt;
      Ys[cc * 108 + u * 4 + tt] =
          x[((n * 64 + cc) * 400 + t) * 27 + u] + pe[(cc * 400 + t) * 27 + u];
    }
    __syncthreads();

    if (tid < 216) {
      const int rg = tid / 27, colg = tid % 27;
      u64 acc[8];
      #pragma unroll
      for (int i = 0; i < 8; ++i) acc[i] = 0ull;
      #pragma unroll 4
      for (int cc = 0; cc < 64; ++cc) {
        float4 w = *(const float4*)&WQKT[cc * 32 + rg * 4];
        ulonglong2 y = *(const ulonglong2*)&Ys[cc * 108 + colg * 4];
        u64 wb;
        wb = bcast2(w.x); ffma2(acc[0], wb, y.x); ffma2(acc[1], wb, y.y);
        wb = bcast2(w.y); ffma2(acc[2], wb, y.x); ffma2(acc[3], wb, y.y);
        wb = bcast2(w.z); ffma2(acc[4], wb, y.x); ffma2(acc[5], wb, y.y);
        wb = bcast2(w.w); ffma2(acc[6], wb, y.x); ffma2(acc[7], wb, y.y);
      }
      #pragma unroll
      for (int r = 0; r < 4; ++r) {
        float b = BQK[rg * 4 + r];
        float2 A0 = unpk(acc[r * 2]);
        float2 A1 = unpk(acc[r * 2 + 1]);
        *(float4*)&QKs[(rg * 4 + r) * 108 + colg * 4] =
            make_float4(A0.x + b, A0.y + b, A1.x + b, A1.y + b);
      }
    }
    __syncthreads();

    #pragma unroll
    for (int ii = 0; ii < 4; ++ii) {
      int p = tid + 224 * ii;
      if (p < 729) {
        int u = p / 27, vv = p % 27;
        float acc = 0.f;
        #pragma unroll 4
        for (int c = 0; c < 16; ++c) {
          float4 q = *(const float4*)&QKs[c * 108 + u * 4];
          float4 k = *(const float4*)&QKs[(16 + c) * 108 + vv * 4];
          acc += q.x * k.x + q.y * k.y + q.z * k.z + q.w * k.w;
        }
        if (ii == 0) g0 += acc; else if (ii == 1) g1 += acc;
        else if (ii == 2) g2 += acc; else g3 += acc;
      }
    }
    __syncthreads();
  }

  const int base = (chunk * 64 + n * 2 + s) * 729;
  g_part[base + tid] = g0;
  g_part[base + tid + 224] = g1;
  g_part[base + tid + 448] = g2;
  if (tid + 672 < 729) g_part[base + tid + 672] = g3;
}

// ============================================================================
// Kernel B: reduce 20 partials, tanh scale.
// ============================================================================
__global__ void kB(const float* __restrict__ alphas, const float* __restrict__ att0) {
  int idx = blockIdx.x * 256 + threadIdx.x;
  if (idx >= KN * KS * 729) return;
  int p = idx % 729;
  int s = (idx / 729) & 1;
  float sum = 0.f;
  #pragma unroll
  for (int ch = 0; ch < 20; ++ch) sum += g_part[ch * 46656 + idx];
  g_att[idx] = tanhf(sum * (1.0f / 6400.0f)) * alphas[s] + att0[s * 729 + p];
}

// ============================================================================
// Kernel C: per (n, 4-t tile), 224 threads, 2 CTAs/SM. cols = tt*28+v (112).
// y2: att pair hoisted to 27 u64 regs, inner = bcast LDS.32 + ffma2.
// GEMM: 8o x 4col per thread (16 u64 accs), 1.5 B/MAC.
// smem floats: WB[64][64]@0 (4096) | ATT@4096 (1512) | CAO@5608 CBO@5672
//   CAF@5736 CBF@5800 | XS[64][112]@5864 (7168) | YB[64][112]@13032 (7168)
// total 20200 f = 80800 B
// ============================================================================
__device__ __forceinline__ void kc_y2(float* sm, int S, int colp, int cgrp) {
  const int ATT = 4096, XS = 5864, YB = 13032;
  const int col0 = colp * 2;            // even; pair never straddles a 28-col row
  const int tt = col0 / 28, v0 = col0 % 28;
  u64 ar[27];
  #pragma unroll
  for (int u = 0; u < 27; ++u)
    ar[u] = *(const u64*)&sm[ATT + S * 756 + u * 28 + v0];
  #pragma unroll 4
  for (int ci = 0; ci < 16; ++ci) {
    const int c = cgrp * 16 + ci;
    const float* xr = &sm[XS + c * 112 + tt * 28];
    u64 acc = 0ull;
    #pragma unroll
    for (int u = 0; u < 27; ++u)
      ffma2(acc, bcast2(xr[u]), ar[u]);
    *(u64*)&sm[YB + c * 112 + col0] = acc;
  }
}

__device__ __forceinline__ void kc_gemm(const float* sm, int og, int cg, u64* acc) {
  const int YB = 13032;
  #pragma unroll 4
  for (int k = 0; k < 64; ++k) {
    const float* wr = &sm[k * 64 + og * 8];
    float4 wa = *(const float4*)wr;
    float4 wb = *(const float4*)(wr + 4);
    ulonglong2 y = *(const ulonglong2*)&sm[YB + k * 112 + cg * 4];
    u64 w;
    w = bcast2(wa.x); ffma2(acc[0],  w, y.x); ffma2(acc[1],  w, y.y);
    w = bcast2(wa.y); ffma2(acc[2],  w, y.x); ffma2(acc[3],  w, y.y);
    w = bcast2(wa.z); ffma2(acc[4],  w, y.x); ffma2(acc[5],  w, y.y);
    w = bcast2(wa.w); ffma2(acc[6],  w, y.x); ffma2(acc[7],  w, y.y);
    w = bcast2(wb.x); ffma2(acc[8],  w, y.x); ffma2(acc[9],  w, y.y);
    w = bcast2(wb.y); ffma2(acc[10], w, y.x); ffma2(acc[11], w, y.y);
    w = bcast2(wb.z); ffma2(acc[12], w, y.x); ffma2(acc[13], w, y.y);
    w = bcast2(wb.w); ffma2(acc[14], w, y.x); ffma2(acc[15], w, y.y);
  }
}

__global__ void __launch_bounds__(224, 2)
kC(const float* __restrict__ x,
   const float* __restrict__ W_out, const float* __restrict__ b_out,
   const float* __restrict__ gm_out, const float* __restrict__ be_out,
   const float* __restrict__ m_out, const float* __restrict__ v_out,
   const float* __restrict__ W_ff, const float* __restrict__ b_ff,
   const float* __restrict__ gm_ff, const float* __restrict__ be_ff,
   const float* __restrict__ m_ff, const float* __restrict__ v_ff) {
  extern __shared__ float sm[];
  const int ATT = 4096, CAO = 5608, CBO = 5672, CAF = 5736, CBF = 5800;
  const int XS = 5864, YB = 13032;
  const int tid = threadIdx.x;
  const int n = blockIdx.y;
  const int t0 = blockIdx.x * 4;

  for (int j = tid; j < 7168; j += 224) {
    int c = j / 112, col = j % 112, tt = col / 28, v = col % 28;
    sm[XS + j] = (v < 27) ? x[((n * 64 + c) * 400 + t0 + tt) * 27 + v] : 0.f;
  }
  for (int j = tid; j < 1512; j += 224) {
    int s = j / 756, r = j % 756, u = r / 28, v = r % 28;
    sm[ATT + j] = (v < 27) ? g_att[(n * 2 + s) * 729 + u * 27 + v] : 0.f;
  }
  for (int j = tid; j < 4096; j += 224) {      // W_out s=0, [k][o]
    int k = j >> 6, o = j & 63;
    sm[j] = W_out[o * 128 + k];
  }
  if (tid < 64) {
    float a = gm_out[tid] * rsqrtf(v_out[tid] + 1e-5f);
    sm[CAO + tid] = a;
    sm[CBO + tid] = (b_out[tid] - m_out[tid]) * a + be_out[tid];
    float af = gm_ff[tid] * rsqrtf(v_ff[tid] + 1e-5f);
    sm[CAF + tid] = af;
    sm[CBF + tid] = (b_ff[tid] - m_ff[tid]) * af + be_ff[tid];
  }
  __syncthreads();

  const int colp = tid % 56, cgrp = tid / 56;  // y2 map
  const int og = tid / 28, cg = tid % 28;      // GEMM map
  u64 acc[16];
  #pragma unroll
  for (int i = 0; i < 16; ++i) acc[i] = 0ull;

  // s = 0
  kc_y2(sm, 0, colp, cgrp);
  __syncthreads();
  kc_gemm(sm, og, cg, acc);
  __syncthreads();

  // s = 1: swap weight half, recompute y2
  for (int j = tid; j < 4096; j += 224) {
    int k = j >> 6, o = j & 63;
    sm[j] = W_out[o * 128 + 64 + k];
  }
  kc_y2(sm, 1, colp, cgrp);
  __syncthreads();
  kc_gemm(sm, og, cg, acc);
  __syncthreads();

  // epilogue 1: y3 -> YB ; load W_ff
  for (int j = tid; j < 4096; j += 224) {
    int k = j >> 6, o = j & 63;
    sm[j] = W_ff[o * 64 + k];
  }
  #pragma unroll
  for (int jo = 0; jo < 8; ++jo) {
    int o = og * 8 + jo;
    float a = sm[CAO + o], b = sm[CBO + o];
    float2 A0 = unpk(acc[jo * 2]);
    float2 A1 = unpk(acc[jo * 2 + 1]);
    float4 xv = *(const float4*)&sm[XS + o * 112 + cg * 4];
    float r0 = lrelu(xv.x + A0.x * a + b);
    float r1 = lrelu(xv.y + A0.y * a + b);
    float r2 = lrelu(xv.z + A1.x * a + b);
    float r3 = lrelu(xv.w + A1.y * a + b);
    *(float4*)&sm[YB + o * 112 + cg * 4] = make_float4(r0, r1, r2, r3);
  }
  #pragma unroll
  for (int i = 0; i < 16; ++i) acc[i] = 0ull;
  __syncthreads();

  kc_gemm(sm, og, cg, acc);

  // epilogue 2: y4 -> global
  #pragma unroll
  for (int jo = 0; jo < 8; ++jo) {
    int o = og * 8 + jo;
    float a = sm[CAF + o], b = sm[CBF + o];
    float2 A0 = unpk(acc[jo * 2]);
    float2 A1 = unpk(acc[jo * 2 + 1]);
    float rv[4] = {A0.x, A0.y, A1.x, A1.y};
    #pragma unroll
    for (int e = 0; e < 4; ++e) {
      int col = cg * 4 + e;
      int tt = col / 28, v = col % 28;
      if (v < 27) {
        float r = lrelu(sm[XS + o * 112 + col] + rv[e] * a + b);
        g_y4[((long)(n * 64 + o) * 400 + t0 + tt) * 27 + v] = r;
      }
    }
  }
}

// ============================================================================
// Kernel D: temporal conv. 448 threads, 8o x 4col (16 accs), 2 CTAs/SM.
// smem: WB[96][64]@0 (6144) | YS[64][280]@6144 (17920) | CAT@24064 CBT@24128
// total 24192 f = 96768 B
// ============================================================================
__global__ void __launch_bounds__(448, 2)
kD(const float* __restrict__ W_t, const float* __restrict__ b_t,
   const float* __restrict__ gm_t, const float* __restrict__ be_t,
   const float* __restrict__ m_t, const float* __restrict__ v_t,
   float* __restrict__ out) {
  extern __shared__ float sm[];
  const int YS = 6144, CAT = 24064, CBT = 24128;
  const int tid = threadIdx.x;
  const int n = blockIdx.y;
  const int t0 = blockIdx.x * 8;

  for (int j = tid; j < 17920; j += 448) {
    int i = j / 280, r = j % 280, tl = r / 28, v = r % 28;
    int t = t0 - 1 + tl;
    sm[YS + j] = (v < 27 && t >= 0 && t < 400)
                 ? g_y4[((long)(n * 64 + i) * 400 + t) * 27 + v] : 0.f;
  }
  if (tid < 64) {
    float a = gm_t[tid] * rsqrtf(v_t[tid] + 1e-5f);
    sm[CAT + tid] = a;
    sm[CBT + tid] = (b_t[tid] - m_t[tid]) * a + be_t[tid];
  }

  const int og = tid / 56, cg = tid % 56;   // col group: cols cg*4 .. cg*4+3
  u64 acc[16];
  #pragma unroll
  for (int i = 0; i < 16; ++i) acc[i] = 0ull;

  for (int p = 0; p < 2; ++p) {
    __syncthreads();
    for (int j = tid; j < 6144; j += 448) {
      int o = j / 96, r = j % 96;          // r = il*3+kk
      sm[r * 64 + o] = W_t[o * 192 + p * 96 + r];
    }
    __syncthreads();

    #pragma unroll 2
    for (int il = 0; il < 32; ++il) {
      const int i = p * 32 + il;
      #pragma unroll
      for (int kk = 0; kk < 3; ++kk) {
        const float* wr = &sm[(il * 3 + kk) * 64 + og * 8];
        float4 wa = *(const float4*)wr;
        float4 wb = *(const float4*)(wr + 4);
        ulonglong2 y = *(const ulonglong2*)&sm[YS + i * 280 + kk * 28 + cg * 4];
        u64 w;
        w = bcast2(wa.x); ffma2(acc[0],  w, y.x); ffma2(acc[1],  w, y.y);
        w = bcast2(wa.y); ffma2(acc[2],  w, y.x); ffma2(acc[3],  w, y.y);
        w = bcast2(wa.z); ffma2(acc[4],  w, y.x); ffma2(acc[5],  w, y.y);
        w = bcast2(wa.w); ffma2(acc[6],  w, y.x); ffma2(acc[7],  w, y.y);
        w = bcast2(wb.x); ffma2(acc[8],  w, y.x); ffma2(acc[9],  w, y.y);
        w = bcast2(wb.y); ffma2(acc[10], w, y.x); ffma2(acc[11], w, y.y);
        w = bcast2(wb.z); ffma2(acc[12], w, y.x); ffma2(acc[13], w, y.y);
        w = bcast2(wb.w); ffma2(acc[14], w, y.x); ffma2(acc[15], w, y.y);
      }
    }
  }

  #pragma unroll
  for (int jo = 0; jo < 8; ++jo) {
    int o = og * 8 + jo;
    float a = sm[CAT + o], b = sm[CBT + o];
    float2 A0 = unpk(acc[jo * 2]);
    float2 A1 = unpk(acc[jo * 2 + 1]);
    float rv[4] = {A0.x, A0.y, A1.x, A1.y};
    #pragma unroll
    for (int e = 0; e < 4; ++e) {
      int col = cg * 4 + e;
      int tt = col / 28, v = col % 28;
      if (v < 27) {
        float y = sm[YS + o * 280 + (tt + 1) * 28 + v];   // residual y4
        float r = lrelu(y + rv[e] * a + b);
        out[((long)(n * 64 + o) * 400 + t0 + tt) * 27 + v] = r;
      }
    }
  }
}

// ============================================================================
extern "C" void kernel_launch(void* const* d_in, const int* in_sizes, int n_in,
                              void* d_out, int out_size) {
  const float* x      = (const float*)d_in[0];
  const float* pe     = (const float*)d_in[1];
  const float* W_in   = (const float*)d_in[2];
  const float* b_in   = (const float*)d_in[3];
  const float* alphas = (const float*)d_in[4];
  const float* att0   = (const float*)d_in[5];
  const float* W_out  = (const float*)d_in[6];
  const float* b_out  = (const float*)d_in[7];
  const float* g_out  = (const float*)d_in[8];
  const float* be_out = (const float*)d_in[9];
  const float* m_out  = (const float*)d_in[10];
  const float* v_out  = (const float*)d_in[11];
  const float* W_ff   = (const float*)d_in[12];
  const float* b_ff   = (const float*)d_in[13];
  const float* g_ff   = (const float*)d_in[14];
  const float* be_ff  = (const float*)d_in[15];
  const float* m_ff   = (const float*)d_in[16];
  const float* v_ff   = (const float*)d_in[17];
  const float* W_t    = (const float*)d_in[18];
  const float* b_t    = (const float*)d_in[19];
  const float* g_t    = (const float*)d_in[20];
  const float* be_t   = (const float*)d_in[21];
  const float* m_t    = (const float*)d_in[22];
  const float* v_t    = (const float*)d_in[23];
  float* out = (float*)d_out;

  cudaFuncSetAttribute(kA, cudaFuncAttributeMaxDynamicSharedMemorySize, 49792);
  cudaFuncSetAttribute(kC, cudaFuncAttributeMaxDynamicSharedMemorySize, 80800);
  cudaFuncSetAttribute(kD, cudaFuncAttributeMaxDynamicSharedMemorySize, 96768);

  kA<<<dim3(20, 2, 32), 224, 49792>>>(x, pe, W_in, b_in);
  kB<<<(KN * KS * 729 + 255) / 256, 256>>>(alphas, att0);
  kC<<<dim3(100, 32), 224, 80800>>>(x, W_out, b_out, g_out, be_out, m_out, v_out,
                                    W_ff, b_ff, g_ff, be_ff, m_ff, v_ff);
  kD<<<dim3(50, 32), 448, 96768>>>(W_t, b_t, g_t, be_t, m_t, v_t, out);
}